// round 1
// baseline (speedup 1.0000x reference)
#include <cuda_runtime.h>
#include <math.h>

// Problem constants
#define BATCH   32
#define H       384
#define KK      378
#define NS      7
#define NSHIFT  49
#define TILE    54          // 378 = 7 * 54
#define PATCH   60          // TILE + 6
#define NTILE   7
#define NTOT_D  (32.0 * 378.0 * 378.0)   // 4,572,288

// Global scratch (no allocations allowed)
__device__ double g_sums[NSHIFT * 4];   // per shift: Sd, Sd2, n, Sm
__device__ double g_abs;
__device__ int    g_idx;

__global__ void init_kernel() {
    int t = threadIdx.x;
    if (t < NSHIFT * 4) g_sums[t] = 0.0;
    if (t == 0) { g_abs = 0.0; g_idx = 0; }
}

// Per-tile stats: block = (tile_x, tile_y, batch), 7 warps, warp w owns u=w,
// each lane accumulates 7 v-shifts over lane-strided tile pixels.
__global__ __launch_bounds__(224) void stats_kernel(
    const float* __restrict__ pred, const float* __restrict__ target)
{
    __shared__ float sT[PATCH * PATCH];
    __shared__ float sP[TILE * TILE];

    const int x0 = blockIdx.x * TILE;
    const int y0 = blockIdx.y * TILE;
    const int b  = blockIdx.z;
    const float* tb = target + (size_t)b * H * H;
    const float* pb = pred   + (size_t)b * H * H;
    const int tid = threadIdx.x;

    // Stage target patch (60x60) and pred tile (54x54, offset +3) into SMEM
    for (int k = tid; k < PATCH * PATCH; k += 224) {
        int yy = k / PATCH, xx = k - yy * PATCH;
        sT[k] = tb[(y0 + yy) * H + (x0 + xx)];
    }
    for (int k = tid; k < TILE * TILE; k += 224) {
        int i = k / TILE, j = k - i * TILE;
        sP[k] = pb[(y0 + i + 3) * H + (x0 + j + 3)];
    }
    __syncthreads();

    const int w    = tid >> 5;   // u shift for this warp
    const int lane = tid & 31;

    float sd[NS], sd2[NS], cn[NS], sm[NS];
#pragma unroll
    for (int v = 0; v < NS; v++) { sd[v] = 0.f; sd2[v] = 0.f; cn[v] = 0.f; sm[v] = 0.f; }

    for (int f = lane; f < TILE * TILE; f += 32) {
        int i = f / TILE, j = f - i * TILE;
        float p = sP[f];
        const float* row = &sT[(i + w) * PATCH + j];
#pragma unroll
        for (int v = 0; v < NS; v++) {
            float t = row[v];
            float d = t - p;
            sd[v]  += d;
            sd2[v]  = fmaf(d, d, sd2[v]);
            if (t > 5.0f) { cn[v] += 1.0f; sm[v] += d; }
        }
    }

    // Warp butterfly reduce, lane 0 commits per-shift partials as doubles
#pragma unroll
    for (int v = 0; v < NS; v++) {
        float a0 = sd[v], a1 = sd2[v], a2 = cn[v], a3 = sm[v];
        for (int o = 16; o; o >>= 1) {
            a0 += __shfl_xor_sync(0xffffffffu, a0, o);
            a1 += __shfl_xor_sync(0xffffffffu, a1, o);
            a2 += __shfl_xor_sync(0xffffffffu, a2, o);
            a3 += __shfl_xor_sync(0xffffffffu, a3, o);
        }
        if (lane == 0) {
            int s = w * NS + v;
            atomicAdd(&g_sums[s * 4 + 0], (double)a0);
            atomicAdd(&g_sums[s * 4 + 1], (double)a1);
            atomicAdd(&g_sums[s * 4 + 2], (double)a2);
            atomicAdd(&g_sums[s * 4 + 3], (double)a3);
        }
    }
}

// cmse per shift, argmin (first-min tiebreak like jnp.argmin), write cPSNR
__global__ void argmin_kernel(float* out) {
    __shared__ double scmse[64];
    __shared__ int    sidx[64];
    int t = threadIdx.x;
    double c = 1e300;
    if (t < NSHIFT) {
        double Sd  = g_sums[t * 4 + 0];
        double Sd2 = g_sums[t * 4 + 1];
        double n   = g_sums[t * 4 + 2];
        double Sm  = g_sums[t * 4 + 3];
        double b   = Sm / n;
        c = (Sd2 - 2.0 * b * Sd + NTOT_D * b * b) / n;
    }
    scmse[t] = c; sidx[t] = t;
    __syncthreads();
    for (int o = 32; o; o >>= 1) {
        if (t < o) {
            if (scmse[t + o] < scmse[t]) { scmse[t] = scmse[t + o]; sidx[t] = sidx[t + o]; }
        }
        __syncthreads();
    }
    if (t == 0) {
        g_idx  = sidx[0];
        out[0] = (float)(-10.0 * log10(scmse[0]));
    }
}

// MAE over the winning shift only
__global__ void mae_kernel(const float* __restrict__ pred, const float* __restrict__ target) {
    const int idx = g_idx;
    const int u = idx / NS, v = idx - (idx / NS) * NS;
    const int total = BATCH * KK * KK;

    float acc = 0.f;
    for (int f = blockIdx.x * blockDim.x + threadIdx.x; f < total;
         f += gridDim.x * blockDim.x) {
        int b = f / (KK * KK);
        int r = f - b * (KK * KK);
        int i = r / KK, j = r - i * KK;
        float p = pred  [(size_t)b * H * H + (i + 3) * H + (j + 3)];
        float t = target[(size_t)b * H * H + (i + u) * H + (j + v)];
        acc += fabsf(t - p);
    }
    for (int o = 16; o; o >>= 1) acc += __shfl_xor_sync(0xffffffffu, acc, o);

    __shared__ float ssum[32];
    int lane = threadIdx.x & 31, w = threadIdx.x >> 5;
    if (lane == 0) ssum[w] = acc;
    __syncthreads();
    if (w == 0) {
        float a = (lane < (int)(blockDim.x >> 5)) ? ssum[lane] : 0.f;
        for (int o = 16; o; o >>= 1) a += __shfl_xor_sync(0xffffffffu, a, o);
        if (lane == 0) atomicAdd(&g_abs, (double)a);
    }
}

__global__ void final_kernel(float* out) {
    out[1] = (float)(g_abs / NTOT_D);
}

extern "C" void kernel_launch(void* const* d_in, const int* in_sizes, int n_in,
                              void* d_out, int out_size) {
    const float* pred   = (const float*)d_in[0];
    const float* target = (const float*)d_in[1];
    // d_in[2] = blended_target: unused by the reference
    float* out = (float*)d_out;

    init_kernel<<<1, 256>>>();
    stats_kernel<<<dim3(NTILE, NTILE, BATCH), 224>>>(pred, target);
    argmin_kernel<<<1, 64>>>(out);
    mae_kernel<<<1024, 256>>>(pred, target);
    final_kernel<<<1, 1>>>(out);
}